// round 4
// baseline (speedup 1.0000x reference)
#include <cuda_runtime.h>
#include <math.h>

#define LEVEL 16
#define TPB 256
#define NBLK_R 4096           // reduce blocks (exact: NBLK_R * TPB == M4)

// Per-block partial sums from the reduce pass. Every slot is overwritten
// deterministically on every launch — no init kernel, no atomics.
__device__ double g_partials[NBLK_R];

// ---------------------------------------------------------------------------
// Pass 1: partials[b] = sum over this block's columns of | sum_t x[t, j] |
// Exact grid: one float4 column per thread, 16 loads batched (MLP=16).
// Forward order + __ldcg so the tail of the input remains L2-resident for
// the scan pass (L2 survives kernel boundaries on sm_103a).
// ---------------------------------------------------------------------------
__global__ void __launch_bounds__(TPB) reduce_kernel(const float4* __restrict__ x, int M4) {
    int j = blockIdx.x * TPB + threadIdx.x;

    float acc = 0.0f;
    if (j < M4) {
        float sx = 0.f, sy = 0.f, sz = 0.f, sw = 0.f;
#pragma unroll
        for (int t = 0; t < LEVEL; t++) {
            float4 v = __ldcg(&x[(size_t)t * M4 + j]);
            sx += v.x; sy += v.y; sz += v.z; sw += v.w;
        }
        acc = fabsf(sx) + fabsf(sy) + fabsf(sz) + fabsf(sw);
    }

#pragma unroll
    for (int o = 16; o > 0; o >>= 1)
        acc += __shfl_down_sync(0xFFFFFFFFu, acc, o);

    __shared__ float warp_sums[TPB / 32];
    int lane = threadIdx.x & 31;
    int wid  = threadIdx.x >> 5;
    if (lane == 0) warp_sums[wid] = acc;
    __syncthreads();

    if (wid == 0) {
        acc = (lane < TPB / 32) ? warp_sums[lane] : 0.0f;
#pragma unroll
        for (int o = 16; o > 0; o >>= 1)
            acc += __shfl_down_sync(0xFFFFFFFFu, acc, o);
        if (lane == 0) g_partials[blockIdx.x] = (double)acc;
    }
}

// One ST-BIF neuron step (matches reference: neg overrides pos).
__device__ __forceinline__ float bif_step(float& v, float& T, float xt, float v_th) {
    v += xt;
    float s = 0.0f;
    if (v - v_th >= 0.0f && T - 15.0f < 0.0f) s = 1.0f;
    if (v < 0.0f && T > 0.0f)                 s = -1.0f;
    v -= v_th * s;
    T += s;
    return s;
}

// ---------------------------------------------------------------------------
// Pass 2: per-column 16-step scan in two half-batches of 8 (MLP=8, ~56 regs,
// 4 CTAs/SM => occ 50%). Reverse j order to hit the L2 residue from pass 1;
// __ldcs/__stcs keep this pass's own traffic evict-first.
// ---------------------------------------------------------------------------
__global__ void __launch_bounds__(TPB, 4) scan_kernel(const float4* __restrict__ x,
                                                      float4* __restrict__ out, int M4) {
    // Preamble: warp 0 sums the 4096 partials (32 KB, L2-hot), computes v_th.
    __shared__ float s_vth;
    if (threadIdx.x < 32) {
        double d = 0.0;
        for (int i = threadIdx.x; i < NBLK_R; i += 32)
            d += g_partials[i];
#pragma unroll
        for (int o = 16; o > 0; o >>= 1)
            d += __shfl_down_sync(0xFFFFFFFFu, d, o);
        if (threadIdx.x == 0) {
            double mean = d / (4.0 * (double)M4);
            s_vth = (float)(mean * 2.0 / sqrt(15.0));
        }
    }
    __syncthreads();
    float v_th = s_vth;

    // Reverse block mapping: block 0 handles the highest j range.
    int jblk = gridDim.x - 1 - blockIdx.x;
    int j = jblk * TPB + threadIdx.x;
    if (j >= M4) return;

    float vx = 0.5f * v_th, vy = vx, vz = vx, vw = vx;
    float Tx = 0.f, Ty = 0.f, Tz = 0.f, Tw = 0.f;

#pragma unroll
    for (int half = 0; half < 2; half++) {
        // Burst-read 8 time steps (32 data regs in flight).
        float4 r[8];
#pragma unroll
        for (int t = 0; t < 8; t++)
            r[t] = __ldcs(&x[(size_t)(half * 8 + t) * M4 + j]);

#pragma unroll
        for (int t = 0; t < 8; t++) {
            float4 o;
            o.x = bif_step(vx, Tx, r[t].x, v_th) * v_th;
            o.y = bif_step(vy, Ty, r[t].y, v_th) * v_th;
            o.z = bif_step(vz, Tz, r[t].z, v_th) * v_th;
            o.w = bif_step(vw, Tw, r[t].w, v_th) * v_th;
            __stcs(&out[(size_t)(half * 8 + t) * M4 + j], o);
        }
    }
}

extern "C" void kernel_launch(void* const* d_in, const int* in_sizes, int n_in,
                              void* d_out, int out_size) {
    const float4* x = (const float4*)d_in[0];
    float4* out = (float4*)d_out;

    int n_total = in_sizes[0];         // 32*2048*1024
    int M4 = n_total / LEVEL / 4;      // 1,048,576 float4 columns

    reduce_kernel<<<NBLK_R, TPB>>>(x, M4);          // NBLK_R*TPB == M4 exactly
    scan_kernel<<<(M4 + TPB - 1) / TPB, TPB>>>(x, out, M4);
}

// round 5
// speedup vs baseline: 1.0775x; 1.0775x over previous
#include <cuda_runtime.h>
#include <math.h>

#define LEVEL 16
#define NBLK_R 1024           // reduce blocks (also partials count)
#define TPB 256

// Per-block partial sums from the reduce pass. Every slot is overwritten
// deterministically on every launch — no init kernel, no atomics.
__device__ double g_partials[NBLK_R];

// ---------------------------------------------------------------------------
// Pass 1: partials[b] = sum over this block's j of | sum_t x[t, j] |
// Forward grid-stride order + __ldcg so the tail of the input remains
// L2-resident for the scan pass (L2 survives kernel boundaries on sm_103a).
// ---------------------------------------------------------------------------
__global__ void reduce_kernel(const float4* __restrict__ x, int M4) {
    int tid = blockIdx.x * blockDim.x + threadIdx.x;
    int stride = gridDim.x * blockDim.x;

    float acc = 0.0f;
    for (int j = tid; j < M4; j += stride) {
        float sx = 0.f, sy = 0.f, sz = 0.f, sw = 0.f;
#pragma unroll
        for (int t = 0; t < LEVEL; t++) {
            float4 v = __ldcg(&x[(size_t)t * M4 + j]);
            sx += v.x; sy += v.y; sz += v.z; sw += v.w;
        }
        acc += fabsf(sx) + fabsf(sy) + fabsf(sz) + fabsf(sw);
    }

#pragma unroll
    for (int o = 16; o > 0; o >>= 1)
        acc += __shfl_down_sync(0xFFFFFFFFu, acc, o);

    __shared__ float warp_sums[TPB / 32];
    int lane = threadIdx.x & 31;
    int wid  = threadIdx.x >> 5;
    if (lane == 0) warp_sums[wid] = acc;
    __syncthreads();

    if (wid == 0) {
        acc = (lane < TPB / 32) ? warp_sums[lane] : 0.0f;
#pragma unroll
        for (int o = 16; o > 0; o >>= 1)
            acc += __shfl_down_sync(0xFFFFFFFFu, acc, o);
        if (lane == 0) g_partials[blockIdx.x] = (double)acc;
    }
}

// One ST-BIF neuron step (matches reference: neg overrides pos).
__device__ __forceinline__ float bif_step(float& v, float& T, float xt, float v_th) {
    v += xt;
    float s = 0.0f;
    if (v - v_th >= 0.0f && T - 15.0f < 0.0f) s = 1.0f;
    if (v < 0.0f && T > 0.0f)                 s = -1.0f;
    v -= v_th * s;
    T += s;
    return s;
}

// ---------------------------------------------------------------------------
// Pass 2: per-column 16-step scan. ALL 16 loads batched up front (MLP=16),
// issued BEFORE the v_th preamble so the preamble latency hides under the
// load burst. Stores use __stwt (write-through) so the output stream does
// NOT write-allocate in L2 and evict the input residue left by pass 1.
// Reverse j order so the first waves consume the hottest L2 lines.
// ---------------------------------------------------------------------------
__global__ void __launch_bounds__(TPB) scan_kernel(const float4* __restrict__ x,
                                                   float4* __restrict__ out, int M4) {
    // Reverse block mapping: block 0 handles the highest j range.
    int jblk = gridDim.x - 1 - blockIdx.x;
    int j = jblk * TPB + threadIdx.x;

    // Burst-read all 16 time steps first (64 data regs in flight).
    float4 r[LEVEL];
    if (j < M4) {
#pragma unroll
        for (int t = 0; t < LEVEL; t++)
            r[t] = __ldcs(&x[(size_t)t * M4 + j]);
    }

    // Preamble overlaps with the in-flight burst: warp 0 sums the partials.
    __shared__ float s_vth;
    if (threadIdx.x < 32) {
        double d = 0.0;
#pragma unroll
        for (int i = threadIdx.x; i < NBLK_R; i += 32)
            d += g_partials[i];
#pragma unroll
        for (int o = 16; o > 0; o >>= 1)
            d += __shfl_down_sync(0xFFFFFFFFu, d, o);
        if (threadIdx.x == 0) {
            double mean = d / (4.0 * (double)M4);
            s_vth = (float)(mean * 2.0 / sqrt(15.0));
        }
    }
    __syncthreads();
    float v_th = s_vth;

    if (j >= M4) return;

    float vx = 0.5f * v_th, vy = vx, vz = vx, vw = vx;
    float Tx = 0.f, Ty = 0.f, Tz = 0.f, Tw = 0.f;

#pragma unroll
    for (int t = 0; t < LEVEL; t++) {
        float4 o;
        o.x = bif_step(vx, Tx, r[t].x, v_th) * v_th;
        o.y = bif_step(vy, Ty, r[t].y, v_th) * v_th;
        o.z = bif_step(vz, Tz, r[t].z, v_th) * v_th;
        o.w = bif_step(vw, Tw, r[t].w, v_th) * v_th;
        __stwt(&out[(size_t)t * M4 + j], o);   // write-through: no L2 allocate
    }
}

extern "C" void kernel_launch(void* const* d_in, const int* in_sizes, int n_in,
                              void* d_out, int out_size) {
    const float4* x = (const float4*)d_in[0];
    float4* out = (float4*)d_out;

    int n_total = in_sizes[0];         // 32*2048*1024
    int M4 = n_total / LEVEL / 4;      // 1,048,576 float4 columns

    reduce_kernel<<<NBLK_R, TPB>>>(x, M4);
    scan_kernel<<<(M4 + TPB - 1) / TPB, TPB>>>(x, out, M4);
}

// round 6
// speedup vs baseline: 1.0933x; 1.0147x over previous
#include <cuda_runtime.h>
#include <math.h>

#define LEVEL 16
#define NBLK_R 1024           // reduce blocks (also partials count)
#define TPB 256

// Per-block partial sums from the reduce pass. Every slot is overwritten
// deterministically on every launch — no init kernel, no atomics.
__device__ double g_partials[NBLK_R];

// ---------------------------------------------------------------------------
// Pass 1: partials[b] = sum over this block's j of | sum_t x[t, j] |
// Forward grid-stride order + __ldcg so the tail of the input remains
// L2-resident for the scan pass (L2 survives kernel boundaries on sm_103a).
// ---------------------------------------------------------------------------
__global__ void reduce_kernel(const float4* __restrict__ x, int M4) {
    int tid = blockIdx.x * blockDim.x + threadIdx.x;
    int stride = gridDim.x * blockDim.x;

    float acc = 0.0f;
    for (int j = tid; j < M4; j += stride) {
        float sx = 0.f, sy = 0.f, sz = 0.f, sw = 0.f;
#pragma unroll
        for (int t = 0; t < LEVEL; t++) {
            float4 v = __ldcg(&x[(size_t)t * M4 + j]);
            sx += v.x; sy += v.y; sz += v.z; sw += v.w;
        }
        acc += fabsf(sx) + fabsf(sy) + fabsf(sz) + fabsf(sw);
    }

#pragma unroll
    for (int o = 16; o > 0; o >>= 1)
        acc += __shfl_down_sync(0xFFFFFFFFu, acc, o);

    __shared__ float warp_sums[TPB / 32];
    int lane = threadIdx.x & 31;
    int wid  = threadIdx.x >> 5;
    if (lane == 0) warp_sums[wid] = acc;
    __syncthreads();

    if (wid == 0) {
        acc = (lane < TPB / 32) ? warp_sums[lane] : 0.0f;
#pragma unroll
        for (int o = 16; o > 0; o >>= 1)
            acc += __shfl_down_sync(0xFFFFFFFFu, acc, o);
        if (lane == 0) g_partials[blockIdx.x] = (double)acc;
    }
}

// One ST-BIF neuron step (matches reference: neg overrides pos).
__device__ __forceinline__ float bif_step(float& v, float& T, float xt, float v_th) {
    v += xt;
    float s = 0.0f;
    if (v - v_th >= 0.0f && T - 15.0f < 0.0f) s = 1.0f;
    if (v < 0.0f && T > 0.0f)                 s = -1.0f;
    v -= v_th * s;
    T += s;
    return s;
}

// ---------------------------------------------------------------------------
// Pass 2: per-column 16-step scan. Preamble first (keeps register pressure
// low: regs ~80, 2 CTAs/SM), then ALL 16 loads batched (MLP=16). Stores use
// __stwt (write-through) so the output stream does not write-allocate in L2
// and evict the input residue left by pass 1. Reverse j order so the first
// waves consume the hottest L2 lines.
// ---------------------------------------------------------------------------
__global__ void __launch_bounds__(TPB) scan_kernel(const float4* __restrict__ x,
                                                   float4* __restrict__ out, int M4) {
    // Preamble: warp 0 sums the 1024 partials (8 KB, L2-hot), computes v_th.
    __shared__ float s_vth;
    if (threadIdx.x < 32) {
        double d = 0.0;
#pragma unroll
        for (int i = threadIdx.x; i < NBLK_R; i += 32)
            d += g_partials[i];
#pragma unroll
        for (int o = 16; o > 0; o >>= 1)
            d += __shfl_down_sync(0xFFFFFFFFu, d, o);
        if (threadIdx.x == 0) {
            double mean = d / (4.0 * (double)M4);
            s_vth = (float)(mean * 2.0 / sqrt(15.0));
        }
    }
    __syncthreads();
    float v_th = s_vth;

    // Reverse block mapping: block 0 handles the highest j range.
    int jblk = gridDim.x - 1 - blockIdx.x;
    int j = jblk * TPB + threadIdx.x;
    if (j >= M4) return;

    // Burst-read all 16 time steps (64 data regs in flight, MLP=16).
    float4 r[LEVEL];
#pragma unroll
    for (int t = 0; t < LEVEL; t++)
        r[t] = __ldcs(&x[(size_t)t * M4 + j]);

    float vx = 0.5f * v_th, vy = vx, vz = vx, vw = vx;
    float Tx = 0.f, Ty = 0.f, Tz = 0.f, Tw = 0.f;

#pragma unroll
    for (int t = 0; t < LEVEL; t++) {
        float4 o;
        o.x = bif_step(vx, Tx, r[t].x, v_th) * v_th;
        o.y = bif_step(vy, Ty, r[t].y, v_th) * v_th;
        o.z = bif_step(vz, Tz, r[t].z, v_th) * v_th;
        o.w = bif_step(vw, Tw, r[t].w, v_th) * v_th;
        __stwt(&out[(size_t)t * M4 + j], o);   // write-through: no L2 allocate
    }
}

extern "C" void kernel_launch(void* const* d_in, const int* in_sizes, int n_in,
                              void* d_out, int out_size) {
    const float4* x = (const float4*)d_in[0];
    float4* out = (float4*)d_out;

    int n_total = in_sizes[0];         // 32*2048*1024
    int M4 = n_total / LEVEL / 4;      // 1,048,576 float4 columns

    reduce_kernel<<<NBLK_R, TPB>>>(x, M4);
    scan_kernel<<<(M4 + TPB - 1) / TPB, TPB>>>(x, out, M4);
}

// round 7
// speedup vs baseline: 1.1237x; 1.0279x over previous
#include <cuda_runtime.h>
#include <math.h>

#define LEVEL 16
#define NBLK_R 1024           // reduce blocks (also partials count)
#define TPB_R 256             // reduce block size
#define TPB_S 128             // scan block size (small CTAs -> phase desync)

// Per-block partial sums from the reduce pass. Every slot is overwritten
// deterministically on every launch — no init kernel, no atomics.
__device__ double g_partials[NBLK_R];

// ---------------------------------------------------------------------------
// Pass 1: partials[b] = sum over this block's j of | sum_t x[t, j] |
// Forward grid-stride order + __ldcg so the tail of the input remains
// L2-resident for the scan pass (L2 survives kernel boundaries on sm_103a).
// ---------------------------------------------------------------------------
__global__ void reduce_kernel(const float4* __restrict__ x, int M4) {
    int tid = blockIdx.x * blockDim.x + threadIdx.x;
    int stride = gridDim.x * blockDim.x;

    float acc = 0.0f;
    for (int j = tid; j < M4; j += stride) {
        float sx = 0.f, sy = 0.f, sz = 0.f, sw = 0.f;
#pragma unroll
        for (int t = 0; t < LEVEL; t++) {
            float4 v = __ldcg(&x[(size_t)t * M4 + j]);
            sx += v.x; sy += v.y; sz += v.z; sw += v.w;
        }
        acc += fabsf(sx) + fabsf(sy) + fabsf(sz) + fabsf(sw);
    }

#pragma unroll
    for (int o = 16; o > 0; o >>= 1)
        acc += __shfl_down_sync(0xFFFFFFFFu, acc, o);

    __shared__ float warp_sums[TPB_R / 32];
    int lane = threadIdx.x & 31;
    int wid  = threadIdx.x >> 5;
    if (lane == 0) warp_sums[wid] = acc;
    __syncthreads();

    if (wid == 0) {
        acc = (lane < TPB_R / 32) ? warp_sums[lane] : 0.0f;
#pragma unroll
        for (int o = 16; o > 0; o >>= 1)
            acc += __shfl_down_sync(0xFFFFFFFFu, acc, o);
        if (lane == 0) g_partials[blockIdx.x] = (double)acc;
    }
}

// One ST-BIF neuron step (matches reference: neg overrides pos).
__device__ __forceinline__ float bif_step(float& v, float& T, float xt, float v_th) {
    v += xt;
    float s = 0.0f;
    if (v - v_th >= 0.0f && T - 15.0f < 0.0f) s = 1.0f;
    if (v < 0.0f && T > 0.0f)                 s = -1.0f;
    v -= v_th * s;
    T += s;
    return s;
}

// ---------------------------------------------------------------------------
// Pass 2: per-column 16-step scan. Preamble first (low register pressure),
// then ALL 16 loads batched (MLP=16). Small 128-thread CTAs give ~6 CTAs/SM,
// desynchronizing the load/store phases so read and write requests flow
// concurrently. Reverse j order hits the L2 residue from pass 1;
// __ldcs/__stcs keep this pass's traffic evict-first.
// ---------------------------------------------------------------------------
__global__ void __launch_bounds__(TPB_S) scan_kernel(const float4* __restrict__ x,
                                                     float4* __restrict__ out, int M4) {
    // Preamble: warp 0 sums the 1024 partials (8 KB, L2-hot), computes v_th.
    __shared__ float s_vth;
    if (threadIdx.x < 32) {
        double d = 0.0;
#pragma unroll
        for (int i = threadIdx.x; i < NBLK_R; i += 32)
            d += g_partials[i];
#pragma unroll
        for (int o = 16; o > 0; o >>= 1)
            d += __shfl_down_sync(0xFFFFFFFFu, d, o);
        if (threadIdx.x == 0) {
            double mean = d / (4.0 * (double)M4);
            s_vth = (float)(mean * 2.0 / sqrt(15.0));
        }
    }
    __syncthreads();
    float v_th = s_vth;

    // Reverse block mapping: block 0 handles the highest j range.
    int jblk = gridDim.x - 1 - blockIdx.x;
    int j = jblk * TPB_S + threadIdx.x;
    if (j >= M4) return;

    // Burst-read all 16 time steps (64 data regs in flight, MLP=16).
    float4 r[LEVEL];
#pragma unroll
    for (int t = 0; t < LEVEL; t++)
        r[t] = __ldcs(&x[(size_t)t * M4 + j]);

    float vx = 0.5f * v_th, vy = vx, vz = vx, vw = vx;
    float Tx = 0.f, Ty = 0.f, Tz = 0.f, Tw = 0.f;

#pragma unroll
    for (int t = 0; t < LEVEL; t++) {
        float4 o;
        o.x = bif_step(vx, Tx, r[t].x, v_th) * v_th;
        o.y = bif_step(vy, Ty, r[t].y, v_th) * v_th;
        o.z = bif_step(vz, Tz, r[t].z, v_th) * v_th;
        o.w = bif_step(vw, Tw, r[t].w, v_th) * v_th;
        __stcs(&out[(size_t)t * M4 + j], o);
    }
}

extern "C" void kernel_launch(void* const* d_in, const int* in_sizes, int n_in,
                              void* d_out, int out_size) {
    const float4* x = (const float4*)d_in[0];
    float4* out = (float4*)d_out;

    int n_total = in_sizes[0];         // 32*2048*1024
    int M4 = n_total / LEVEL / 4;      // 1,048,576 float4 columns

    reduce_kernel<<<NBLK_R, TPB_R>>>(x, M4);
    scan_kernel<<<(M4 + TPB_S - 1) / TPB_S, TPB_S>>>(x, out, M4);
}